// round 16
// baseline (speedup 1.0000x reference)
#include <cuda_runtime.h>
#include <cuda_fp16.h>
#include <cstdint>

// Problem constants
constexpr int Bb = 4, Ts = 1024, Cc = 1024, Hh = 8, Dd = 128, Ff = 4096, Ll = 4;
constexpr int Mr = Bb * Ts;  // 4096

// ---------------- scratch (device globals; allocation-free rule) ----------
__device__ float  g_h[(size_t)Mr * Cc];                    // residual fp32
__device__ __half g_qkv[(size_t)3 * Hh * Mr * Dd];         // q,k rows; vT cols
__device__ __half g_xn[(size_t)Mr * Cc];                   // LN out fp16
__device__ __half g_o[(size_t)Mr * Cc];                    // attn out fp16
__device__ __half g_u[(size_t)Mr * Ff];                    // FFN hidden fp16
__device__ __half g_wqkv_h[(size_t)Ll * 3 * Hh * Dd * Cc]; // fp16 weights [N,K]
__device__ __half g_wo_h[(size_t)Ll * Cc * Cc];
__device__ __half g_w1_h[(size_t)Ll * Cc * Ff];
__device__ __half g_w2_h[(size_t)Ll * Ff * Cc];

// ---------------- PTX helpers (sm_80-era; compiles for plain sm_103) ------
__device__ __forceinline__ uint32_t smem_u32(const void* p) {
    uint32_t a;
    asm("{ .reg .u64 t; cvta.to.shared.u64 t, %1; cvt.u32.u64 %0, t; }" : "=r"(a) : "l"(p));
    return a;
}
__device__ __forceinline__ void cp16(uint32_t s, const void* g) {
    asm volatile("cp.async.cg.shared.global [%0], [%1], 16;" :: "r"(s), "l"(g));
}
#define CP_COMMIT() asm volatile("cp.async.commit_group;" ::: "memory")
#define CP_WAIT(n)  asm volatile("cp.async.wait_group %0;" :: "n"(n) : "memory")

#define LDSM4(r, addr) \
    asm volatile("ldmatrix.sync.aligned.m8n8.x4.shared.b16 {%0,%1,%2,%3}, [%4];" \
        : "=r"((r)[0]), "=r"((r)[1]), "=r"((r)[2]), "=r"((r)[3]) : "r"(addr))

#define MMA16816(c, a, b) \
    asm volatile("mma.sync.aligned.m16n8k16.row.col.f32.f16.f16.f32 " \
        "{%0,%1,%2,%3}, {%4,%5,%6,%7}, {%8,%9}, {%0,%1,%2,%3};" \
        : "+f"((c)[0]), "+f"((c)[1]), "+f"((c)[2]), "+f"((c)[3]) \
        : "r"((a)[0]), "r"((a)[1]), "r"((a)[2]), "r"((a)[3]), \
          "r"((b)[0]), "r"((b)[1]))

// ---------------------------------------------------------------------------
// HMMA fp16 GEMM: C[M,N] = A[M,K] * Bt[N,K]^T, fp32 accum.
// Block 128x128, 8 warps (4M x 2N), K-chunks of 64, 3-stage cp.async, occ 2.
// NCH = K/64 (compile-time trip count).
// EPI: 2 fp32 += acc+bias | 4 relu(acc+bias)->fp16 rows
//      5 QKV: z<16 fp16 rows, z>=16 vT transposed via smem staging (ld = Mr)
// ---------------------------------------------------------------------------
constexpr int STG   = 36864;            // 128 rows * 144 B * 2 matrices
constexpr int B_OFF = 18432;
constexpr int SM_MM = 3 * STG;          // 110592

template<int EPI, int NCH>
__global__ void __launch_bounds__(256, 2)
gemm_mma(const __half* __restrict__ A, int lda,
         int aDiv, long long aShi, long long aSlo,
         const __half* __restrict__ B, int ldb,
         int bDiv, long long bShi, long long bSlo,
         float* __restrict__ Cm, int ldc,
         int cDiv, long long cShi, long long cSlo,
         const float* __restrict__ bias)
{
    extern __shared__ char sm[];
    const uint32_t sb = smem_u32(sm);

    const int tid = threadIdx.x;
    const int lane = tid & 31;
    const int warp = tid >> 5;
    const int warpM = warp & 3;
    const int warpN = warp >> 2;

    const int z = blockIdx.z;
    A  += (long long)(z / aDiv) * aShi + (long long)(z % aDiv) * aSlo;
    B  += (long long)(z / bDiv) * bShi + (long long)(z % bDiv) * bSlo;
    const long long cOff = (long long)(z / cDiv) * cShi + (long long)(z % cDiv) * cSlo;

    const int rowBase = blockIdx.y * 128;
    const int colBase = blockIdx.x * 128;

    float acc[2][8][4];
#pragma unroll
    for (int i = 0; i < 2; i++)
#pragma unroll
        for (int j = 0; j < 8; j++)
#pragma unroll
            for (int q = 0; q < 4; q++) acc[i][j][q] = 0.f;

    const int ldr = tid >> 3;            // 0..31
    const int c16 = (tid & 7) * 16;      // byte col in 128B row

    auto load_chunk = [&](int i, int st) {
        const long long k0 = (long long)i * 64;
        const uint32_t sbase = sb + (uint32_t)st * STG;
#pragma unroll
        for (int g = 0; g < 4; g++) {
            const int rr = g * 32 + ldr;
            const uint32_t so = sbase + (uint32_t)(rr * 144 + c16);
            cp16(so,
                 (const char*)(A + (long long)(rowBase + rr) * lda + k0) + c16);
            cp16(so + B_OFF,
                 (const char*)(B + (long long)(colBase + rr) * ldb + k0) + c16);
        }
    };

    load_chunk(0, 0); CP_COMMIT();
    load_chunk(1, 1); CP_COMMIT();

#pragma unroll 4
    for (int i = 0; i < NCH; i++) {
        if (i + 1 < NCH) { CP_WAIT(1); } else { CP_WAIT(0); }
        __syncthreads();
        if (i + 2 < NCH) { load_chunk(i + 2, (i + 2) % 3); CP_COMMIT(); }

        const uint32_t sbase = sb + (uint32_t)(i % 3) * STG;
#pragma unroll
        for (int ks = 0; ks < 4; ks++) {
            uint32_t ah[2][4], bh[8][2];
#pragma unroll
            for (int tm = 0; tm < 2; tm++) {
                const int row = warpM * 32 + tm * 16 + (lane & 15);
                const uint32_t addr =
                    sbase + (uint32_t)(row * 144 + ((lane >> 4) << 4) + ks * 32);
                LDSM4(ah[tm], addr);
            }
#pragma unroll
            for (int gn = 0; gn < 4; gn++) {
                const int n = warpN * 64 + gn * 16 + ((lane >> 4) & 1) * 8 + (lane & 7);
                const uint32_t addr =
                    sbase + (uint32_t)B_OFF +
                    (uint32_t)(n * 144 + ((lane >> 3) & 1) * 16 + ks * 32);
                uint32_t r0[4];
                LDSM4(r0, addr);
                bh[gn * 2][0] = r0[0]; bh[gn * 2][1] = r0[1];
                bh[gn * 2 + 1][0] = r0[2]; bh[gn * 2 + 1][1] = r0[3];
            }
#pragma unroll
            for (int tm = 0; tm < 2; tm++) {
#pragma unroll
                for (int tn = 0; tn < 8; tn++) {
                    MMA16816(acc[tm][tn], ah[tm], bh[tn]);
                }
            }
        }
    }

    const int lr = lane >> 2;
    const int lc = (lane & 3) * 2;

    if (EPI == 5 && blockIdx.z >= 16) {
        // ---- vT epilogue: stage transposed tile in smem, coalesced store ----
        __syncthreads();
        __half* st = (__half*)sm;                // [128 cols][136 halves stride]
#pragma unroll
        for (int tm = 0; tm < 2; tm++) {
#pragma unroll
            for (int tn = 0; tn < 8; tn++) {
                const int lrow = warpM * 32 + tm * 16 + lr;
                const int lcol = warpN * 64 + tn * 8 + lc;
                const float* a = acc[tm][tn];
                st[lcol * 136 + lrow]           = __float2half_rn(a[0]);
                st[(lcol + 1) * 136 + lrow]     = __float2half_rn(a[1]);
                st[lcol * 136 + lrow + 8]       = __float2half_rn(a[2]);
                st[(lcol + 1) * 136 + lrow + 8] = __float2half_rn(a[3]);
            }
        }
        __syncthreads();
        __half* base = (__half*)Cm + cOff;
        const int cr = tid >> 1;
        const int part = tid & 1;
        const uint4* src = (const uint4*)((const char*)st + cr * 272 + part * 128);
        uint4* dst = (uint4*)(base + (long long)(colBase + cr) * Mr + rowBase + part * 64);
#pragma unroll
        for (int i = 0; i < 8; i++) dst[i] = src[i];
        return;
    }

    // ---- standard epilogues from registers ----
    const int rB = rowBase + warpM * 32;
    const int cB = colBase + warpN * 64;
#pragma unroll
    for (int tm = 0; tm < 2; tm++) {
#pragma unroll
        for (int tn = 0; tn < 8; tn++) {
            const int row0 = rB + tm * 16 + lr;
            const int col  = cB + tn * 8 + lc;
            const float* a = acc[tm][tn];
            if (EPI == 2) {
                const float b0 = bias[col], b1 = bias[col + 1];
                float* p0 = Cm + cOff + (long long)row0 * ldc + col;
                float* p1 = Cm + cOff + (long long)(row0 + 8) * ldc + col;
                p0[0] += a[0] + b0;  p0[1] += a[1] + b1;
                p1[0] += a[2] + b0;  p1[1] += a[3] + b1;
            } else if (EPI == 4) {
                const float b0 = bias[col], b1 = bias[col + 1];
                __half* ph = (__half*)Cm + cOff;
#pragma unroll
                for (int half_ = 0; half_ < 2; half_++) {
                    float t0 = a[half_ * 2 + 0] + b0;
                    float t1 = a[half_ * 2 + 1] + b1;
                    t0 = t0 > 0.f ? t0 : 0.f;
                    t1 = t1 > 0.f ? t1 : 0.f;
                    *(__half2*)(ph + (long long)(row0 + half_ * 8) * ldc + col) =
                        __halves2half2(__float2half_rn(t0), __float2half_rn(t1));
                }
            } else {  // EPI 5 (q,k): fp16 row store
                __half* ph = (__half*)Cm + cOff;
#pragma unroll
                for (int half_ = 0; half_ < 2; half_++) {
                    *(__half2*)(ph + (long long)(row0 + half_ * 8) * ldc + col) =
                        __halves2half2(__float2half_rn(a[half_ * 2 + 0]),
                                       __float2half_rn(a[half_ * 2 + 1]));
                }
            }
        }
    }
}

// ---------------------------------------------------------------------------
// Fused attention, occ-2 variant: per block = (h, b, 32 q-rows).
// Phase 1: S[32,1024] = q·k^T, 16 k-tiles of 64 rows, 2-stage.
// Softmax (warp per 4 rows). Phase 2: O[32,128] = P·vT, 16 chunks of 64 k.
// smem: probs 32x2064 | q 32x272 | kv 2x18432.  Total 111616 -> occupancy 2.
// ---------------------------------------------------------------------------
constexpr int PR_STRIDE = 2064;                   // 2048 + 16 pad
constexpr int Q_OFF  = 32 * PR_STRIDE;            // 66048
constexpr int KV_OFF = Q_OFF + 32 * 272;          // 74752
constexpr int KV_STG = 18432;                     // max(64k*272, 128d*144)
constexpr int SM_ATT = KV_OFF + 2 * KV_STG;       // 111616

__global__ void __launch_bounds__(256, 2)
fused_attn(const __half* __restrict__ qkv, float* __restrict__ atts_l,
           __half* __restrict__ o)
{
    extern __shared__ char sm[];
    const uint32_t sb = smem_u32(sm);

    const int tid = threadIdx.x;
    const int lane = tid & 31;
    const int warp = tid >> 5;
    const int warpM = warp & 1;      // 2 M-warps (16 rows each)
    const int warpN = warp >> 1;     // 4 N-warps

    const int qt = blockIdx.x;       // q tile (32 rows): 0..31
    const int hb = blockIdx.y;       // h*Bb + b: 0..31
    const int hh = hb >> 2, bb = hb & 3;

    const long long MrD = (long long)Mr * Dd;
    const __half* qbase = qkv + hh * MrD + (long long)(bb * Ts + qt * 32) * Dd;
    const __half* kbase = qkv + (long long)Hh * MrD + hh * MrD + (long long)(bb * Ts) * Dd;
    const __half* vbase = qkv + 2ll * Hh * MrD + hh * MrD + (long long)(bb * Ts);

    const uint32_t qs = sb + Q_OFF;
    const uint32_t kv = sb + KV_OFF;

    // ---- load q tile (32 rows x 256 B) ----
    {
        const int r = tid >> 3;              // 0..31
        const int c = (tid & 7) * 16;        // 0..112
        cp16(qs + (uint32_t)(r * 272 + c),       (const char*)(qbase + (long long)r * Dd) + c);
        cp16(qs + (uint32_t)(r * 272 + c + 128), (const char*)(qbase + (long long)r * Dd) + c + 128);
    }
    CP_COMMIT();

    // k tile = 64 seq rows x 256 B
    auto load_k = [&](int kt, int st) {
        const int r = tid >> 2;              // 0..63
        const int c = (tid & 3) * 16;        // 0..48
        const char* src = (const char*)(kbase + (long long)(kt * 64 + r) * Dd);
        const uint32_t dst = kv + (uint32_t)st * KV_STG + (uint32_t)(r * 272);
#pragma unroll
        for (int g = 0; g < 4; g++)
            cp16(dst + c + g * 64, src + c + g * 64);
    };
    // v chunk = 128 d-rows x 64 k-cols (128 B payload / row, stride 144)
    auto load_v = [&](int kc, int st) {
        const int r = tid >> 1;              // 0..127
        const int c = (tid & 1) * 16;
        const char* src = (const char*)(vbase + (long long)r * Mr + kc * 64);
        const uint32_t dst = kv + (uint32_t)st * KV_STG + (uint32_t)(r * 144);
#pragma unroll
        for (int g = 0; g < 4; g++)
            cp16(dst + c + g * 32, src + c + g * 32);
    };

    const int lr = lane >> 2;
    const int lc = (lane & 3) * 2;

    // ================= phase 1: scores (16 k-tiles of 64) =================
    load_k(0, 0); CP_COMMIT();
    for (int kt = 0; kt < 16; kt++) {
        CP_WAIT(0);
        __syncthreads();
        if (kt + 1 < 16) { load_k(kt + 1, (kt + 1) & 1); CP_COMMIT(); }

        const uint32_t kbuf = kv + (uint32_t)(kt & 1) * KV_STG;
        float acc[2][4];
#pragma unroll
        for (int j = 0; j < 2; j++)
#pragma unroll
            for (int q = 0; q < 4; q++) acc[j][q] = 0.f;

#pragma unroll
        for (int ks = 0; ks < 8; ks++) {
            uint32_t ah[4], bh[2][2];
            {
                const int row = warpM * 16 + (lane & 15);
                LDSM4(ah, qs + (uint32_t)(row * 272 + ((lane >> 4) << 4) + ks * 32));
            }
            {
                const int n = warpN * 16 + ((lane >> 4) & 1) * 8 + (lane & 7);
                uint32_t r0[4];
                LDSM4(r0, kbuf + (uint32_t)(n * 272 + ((lane >> 3) & 1) * 16 + ks * 32));
                bh[0][0] = r0[0]; bh[0][1] = r0[1];
                bh[1][0] = r0[2]; bh[1][1] = r0[3];
            }
#pragma unroll
            for (int tn = 0; tn < 2; tn++)
                MMA16816(acc[tn], ah, bh[tn]);
        }

        // store fp16 scores into probs smem
#pragma unroll
        for (int tn = 0; tn < 2; tn++) {
            const int row0 = warpM * 16 + lr;
            const int col = kt * 64 + warpN * 16 + tn * 8 + lc;
            const float* a = acc[tn];
#pragma unroll
            for (int half_ = 0; half_ < 2; half_++) {
                *(__half2*)(sm + (row0 + half_ * 8) * PR_STRIDE + col * 2) =
                    __halves2half2(__float2half_rn(a[half_ * 2 + 0]),
                                   __float2half_rn(a[half_ * 2 + 1]));
            }
        }
    }
    __syncthreads();   // all scores in smem

    load_v(0, 0); CP_COMMIT();

    // ================= softmax (warp per 4 rows, coalesced) =================
    {
        const float sc = 0.08838834764831845f;  // 1/sqrt(128)
        for (int rr = 0; rr < 4; rr++) {
            const int row = warp * 4 + rr;
            __half2* prow = (__half2*)(sm + row * PR_STRIDE);
            float v[32];
            float mx = -1e30f;
#pragma unroll
            for (int j = 0; j < 8; j++) {
                const int idx = j * 64 + lane * 2;
                const __half2 a2 = prow[idx];
                const __half2 b2 = prow[idx + 1];
                float f0 = __half2float(__low2half(a2)) * sc;
                float f1 = __half2float(__high2half(a2)) * sc;
                float f2 = __half2float(__low2half(b2)) * sc;
                float f3 = __half2float(__high2half(b2)) * sc;
                v[4 * j] = f0; v[4 * j + 1] = f1; v[4 * j + 2] = f2; v[4 * j + 3] = f3;
                mx = fmaxf(mx, fmaxf(fmaxf(f0, f1), fmaxf(f2, f3)));
            }
#pragma unroll
            for (int off = 16; off; off >>= 1)
                mx = fmaxf(mx, __shfl_xor_sync(0xFFFFFFFFu, mx, off));
            float s = 0.f;
#pragma unroll
            for (int i = 0; i < 32; i++) { v[i] = __expf(v[i] - mx); s += v[i]; }
#pragma unroll
            for (int off = 16; off; off >>= 1)
                s += __shfl_xor_sync(0xFFFFFFFFu, s, off);
            const float inv = 1.f / s;

            float* arow = atts_l + ((long long)hb * Ts + qt * 32 + row) * 1024;
#pragma unroll
            for (int j = 0; j < 8; j++) {
                const int idx = j * 64 + lane * 2;
                const float f0 = v[4 * j] * inv, f1 = v[4 * j + 1] * inv;
                const float f2 = v[4 * j + 2] * inv, f3 = v[4 * j + 3] * inv;
                prow[idx]     = __halves2half2(__float2half_rn(f0), __float2half_rn(f1));
                prow[idx + 1] = __halves2half2(__float2half_rn(f2), __float2half_rn(f3));
                float4 o4 = {f0, f1, f2, f3};
                __stcs((float4*)(arow + j * 128 + lane * 4), o4);
            }
        }
    }
    __syncthreads();

    // ================= phase 2: O = P @ vT (16 chunks of 64 k) =============
    float acc2[4][4];
#pragma unroll
    for (int j = 0; j < 4; j++)
#pragma unroll
        for (int q = 0; q < 4; q++) acc2[j][q] = 0.f;

    for (int kc = 0; kc < 16; kc++) {
        CP_WAIT(0);
        __syncthreads();
        if (kc + 1 < 16) { load_v(kc + 1, (kc + 1) & 1); CP_COMMIT(); }

        const uint32_t vbuf = kv + (uint32_t)(kc & 1) * KV_STG;
#pragma unroll
        for (int ks = 0; ks < 4; ks++) {
            uint32_t ah[4], bh[4][2];
            {
                const int row = warpM * 16 + (lane & 15);
                LDSM4(ah, sb + (uint32_t)(row * PR_STRIDE + kc * 128 +
                                          ((lane >> 4) << 4) + ks * 32));
            }
#pragma unroll
            for (int gn = 0; gn < 2; gn++) {
                const int n = warpN * 32 + gn * 16 + ((lane >> 4) & 1) * 8 + (lane & 7);
                uint32_t r0[4];
                LDSM4(r0, vbuf + (uint32_t)(n * 144 + ((lane >> 3) & 1) * 16 + ks * 32));
                bh[gn * 2][0] = r0[0]; bh[gn * 2][1] = r0[1];
                bh[gn * 2 + 1][0] = r0[2]; bh[gn * 2 + 1][1] = r0[3];
            }
#pragma unroll
            for (int tn = 0; tn < 4; tn++)
                MMA16816(acc2[tn], ah, bh[tn]);
        }
    }

    // epilogue: o fp16 concat layout [B*T, C]
#pragma unroll
    for (int tn = 0; tn < 4; tn++) {
        const int row0 = warpM * 16 + lr;
        const int col = warpN * 32 + tn * 8 + lc;
        const float* a = acc2[tn];
#pragma unroll
        for (int half_ = 0; half_ < 2; half_++) {
            const long long grow = (long long)(bb * Ts + qt * 32 + row0 + half_ * 8);
            *(__half2*)(o + grow * Cc + hh * 128 + col) =
                __halves2half2(__float2half_rn(a[half_ * 2 + 0]),
                               __float2half_rn(a[half_ * 2 + 1]));
        }
    }
}

// ---------------------------------------------------------------------------
// 64x64-tile weight transpose + fp16 convert, float4 loads, 8B stores.
// ---------------------------------------------------------------------------
__global__ void __launch_bounds__(256)
transpose64(const float* __restrict__ W, long long inSlo,
            __half* __restrict__ out, long long outSlo, int K, int N)
{
    const int z = blockIdx.z;
    W += (long long)z * inSlo;
    const long long oOff = (long long)z * outSlo;
    __shared__ float t[64][65];
    const int r  = threadIdx.x >> 4;
    const int c4 = threadIdx.x & 15;
    const int n0 = blockIdx.x * 64, k0 = blockIdx.y * 64;
#pragma unroll
    for (int i = 0; i < 4; i++) {
        const int row = i * 16 + r;
        float4 v = *(const float4*)(W + (long long)(k0 + row) * N + n0 + c4 * 4);
        t[c4 * 4 + 0][row] = v.x;
        t[c4 * 4 + 1][row] = v.y;
        t[c4 * 4 + 2][row] = v.z;
        t[c4 * 4 + 3][row] = v.w;
    }
    __syncthreads();
#pragma unroll
    for (int i = 0; i < 4; i++) {
        const int n = i * 16 + r;
        const float f0 = t[n][c4 * 4 + 0];
        const float f1 = t[n][c4 * 4 + 1];
        const float f2 = t[n][c4 * 4 + 2];
        const float f3 = t[n][c4 * 4 + 3];
        __half2* dst = (__half2*)(out + oOff + (long long)(n0 + n) * K + k0 + c4 * 4);
        dst[0] = __halves2half2(__float2half_rn(f0), __float2half_rn(f1));
        dst[1] = __halves2half2(__float2half_rn(f2), __float2half_rn(f3));
    }
}

// Merged QKV weight transpose (64x64 tiles): z in [0,96).
__global__ void __launch_bounds__(256)
transpose_qkv64(const float* __restrict__ Wq, const float* __restrict__ Wk,
                const float* __restrict__ Wv, __half* __restrict__ outw)
{
    const long long DK  = (long long)Dd * Cc;
    const long long HDK = Hh * DK;
    const int z = blockIdx.z;
    const int s = z >> 5;
    const int zz = z & 31;
    const float* W = (s == 0 ? Wq : s == 1 ? Wk : Wv) + (long long)zz * DK;
    const int l = zz >> 3, hd = zz & 7;
    __half* outp = outw + (long long)l * 3 * HDK + (long long)s * HDK + (long long)hd * DK;

    __shared__ float t[64][65];
    const int r  = threadIdx.x >> 4;
    const int c4 = threadIdx.x & 15;
    const int n0 = blockIdx.x * 64, k0 = blockIdx.y * 64;
#pragma unroll
    for (int i = 0; i < 4; i++) {
        const int row = i * 16 + r;
        float4 v = *(const float4*)(W + (long long)(k0 + row) * Dd + n0 + c4 * 4);
        t[c4 * 4 + 0][row] = v.x;
        t[c4 * 4 + 1][row] = v.y;
        t[c4 * 4 + 2][row] = v.z;
        t[c4 * 4 + 3][row] = v.w;
    }
    __syncthreads();
#pragma unroll
    for (int i = 0; i < 4; i++) {
        const int n = i * 16 + r;
        const float f0 = t[n][c4 * 4 + 0];
        const float f1 = t[n][c4 * 4 + 1];
        const float f2 = t[n][c4 * 4 + 2];
        const float f3 = t[n][c4 * 4 + 3];
        __half2* dst = (__half2*)(outp + (long long)(n0 + n) * Cc + k0 + c4 * 4);
        dst[0] = __halves2half2(__float2half_rn(f0), __float2half_rn(f1));
        dst[1] = __halves2half2(__float2half_rn(f2), __float2half_rn(f3));
    }
}

// ---------------------------------------------------------------------------
// LayerNorm (warp-shuffle reductions).
// MODE 0: fp32 out (streaming). MODE 1: fp16 out. MODE 2: x+pos fused.
// ---------------------------------------------------------------------------
template<int MODE>
__global__ void __launch_bounds__(256)
ln_kernel(const float* __restrict__ x, const float* __restrict__ pos,
          float* __restrict__ y, __half* __restrict__ yh,
          const float* __restrict__ s, const float* __restrict__ b)
{
    __shared__ float red[16];
    const int tid = threadIdx.x;
    const int lane = tid & 31;
    const int warp = tid >> 5;
    const long long row = blockIdx.x;

    float4 v = *(const float4*)(x + row * 1024 + tid * 4);
    if (MODE == 2) {
        const long long prow = row & (Ts - 1);
        float4 p = *(const float4*)(pos + prow * 1024 + tid * 4);
        v.x += p.x; v.y += p.y; v.z += p.z; v.w += p.w;
        *(float4*)(y + row * 1024 + tid * 4) = v;
    }

    float sm1 = v.x + v.y + v.z + v.w;
#pragma unroll
    for (int off = 16; off; off >>= 1)
        sm1 += __shfl_xor_sync(0xFFFFFFFFu, sm1, off);
    if (lane == 0) red[warp] = sm1;
    __syncthreads();
    float tot = 0.f;
#pragma unroll
    for (int w = 0; w < 8; w++) tot += red[w];
    const float mean = tot * (1.f / 1024.f);

    float dx = v.x - mean, dy = v.y - mean, dz = v.z - mean, dw = v.w - mean;
    float sm2 = dx * dx + dy * dy + dz * dz + dw * dw;
#pragma unroll
    for (int off = 16; off; off >>= 1)
        sm2 += __shfl_xor_sync(0xFFFFFFFFu, sm2, off);
    if (lane == 0) red[8 + warp] = sm2;
    __syncthreads();
    float tot2 = 0.f;
#pragma unroll
    for (int w = 0; w < 8; w++) tot2 += red[8 + w];
    const float rs = rsqrtf(tot2 * (1.f / 1024.f) + 1e-5f);

    const int c = tid * 4;
    float t0 = dx * rs * s[c + 0] + b[c + 0];
    float t1 = dy * rs * s[c + 1] + b[c + 1];
    float t2 = dz * rs * s[c + 2] + b[c + 2];
    float t3 = dw * rs * s[c + 3] + b[c + 3];
    if (MODE == 0) {
        float4 o4 = {t0, t1, t2, t3};
        __stcs((float4*)(y + row * 1024 + c), o4);
    } else {
        __half* ph = yh + row * 1024 + c;
        *(__half2*)ph = __halves2half2(__float2half_rn(t0), __float2half_rn(t1));
        *(__half2*)(ph + 2) = __halves2half2(__float2half_rn(t2), __float2half_rn(t3));
    }
}

// ---------------------------------------------------------------------------
extern "C" void kernel_launch(void* const* d_in, const int* in_sizes, int n_in,
                              void* d_out, int out_size)
{
    const float* x     = (const float*)d_in[0];
    const float* pos   = (const float*)d_in[1];
    const float* Wq    = (const float*)d_in[2];
    const float* Wk    = (const float*)d_in[3];
    const float* Wv    = (const float*)d_in[4];
    const float* Wo    = (const float*)d_in[5];
    const float* bo    = (const float*)d_in[6];
    const float* ln1_s = (const float*)d_in[7];
    const float* ln1_b = (const float*)d_in[8];
    const float* ln2_s = (const float*)d_in[9];
    const float* ln2_b = (const float*)d_in[10];
    const float* W1    = (const float*)d_in[11];
    const float* b1    = (const float*)d_in[12];
    const float* W2    = (const float*)d_in[13];
    const float* b2    = (const float*)d_in[14];
    const float* lnf_s = (const float*)d_in[15];
    const float* lnf_b = (const float*)d_in[16];

    float* out  = (float*)d_out;
    float* outx = out;
    float* atts = out + (long long)Mr * Cc;

    float* h;
    __half *qkv, *xn, *o, *u, *wqkv_h, *wo_h, *w1_h, *w2_h;
    cudaGetSymbolAddress((void**)&h,      g_h);
    cudaGetSymbolAddress((void**)&qkv,    g_qkv);
    cudaGetSymbolAddress((void**)&xn,     g_xn);
    cudaGetSymbolAddress((void**)&o,      g_o);
    cudaGetSymbolAddress((void**)&u,      g_u);
    cudaGetSymbolAddress((void**)&wqkv_h, g_wqkv_h);
    cudaGetSymbolAddress((void**)&wo_h,   g_wo_h);
    cudaGetSymbolAddress((void**)&w1_h,   g_w1_h);
    cudaGetSymbolAddress((void**)&w2_h,   g_w2_h);

    cudaFuncSetAttribute((const void*)gemm_mma<2, 16>, cudaFuncAttributeMaxDynamicSharedMemorySize, SM_MM);
    cudaFuncSetAttribute((const void*)gemm_mma<2, 64>, cudaFuncAttributeMaxDynamicSharedMemorySize, SM_MM);
    cudaFuncSetAttribute((const void*)gemm_mma<4, 16>, cudaFuncAttributeMaxDynamicSharedMemorySize, SM_MM);
    cudaFuncSetAttribute((const void*)gemm_mma<5, 16>, cudaFuncAttributeMaxDynamicSharedMemorySize, SM_MM);
    cudaFuncSetAttribute((const void*)fused_attn, cudaFuncAttributeMaxDynamicSharedMemorySize, SM_ATT);

    const long long DK   = (long long)Dd * Cc;       // 131072
    const long long HDK  = Hh * DK;
    const long long HBTT = (long long)Hh * Bb * Ts * Ts;

    // ---- fork a side stream (graph-capturable event fork/join) ----
    cudaStream_t s2;
    cudaStreamCreateWithFlags(&s2, cudaStreamNonBlocking);
    cudaEvent_t eFork, eQkvW, eRestW;
    cudaEventCreateWithFlags(&eFork,  cudaEventDisableTiming);
    cudaEventCreateWithFlags(&eQkvW,  cudaEventDisableTiming);
    cudaEventCreateWithFlags(&eRestW, cudaEventDisableTiming);

    cudaEventRecord(eFork, 0);
    cudaStreamWaitEvent(s2, eFork, 0);

    // side stream: weight transposes
    transpose_qkv64<<<dim3(Dd / 64, Cc / 64, 96), 256, 0, s2>>>(Wq, Wk, Wv, wqkv_h);
    cudaEventRecord(eQkvW, s2);
    transpose64<<<dim3(Cc / 64, Cc / 64, Ll), 256, 0, s2>>>(
        Wo, (long long)Cc * Cc, wo_h, (long long)Cc * Cc, Cc, Cc);
    transpose64<<<dim3(Ff / 64, Cc / 64, Ll), 256, 0, s2>>>(
        W1, (long long)Cc * Ff, w1_h, (long long)Ff * Cc, Cc, Ff);
    transpose64<<<dim3(Cc / 64, Ff / 64, Ll), 256, 0, s2>>>(
        W2, (long long)Ff * Cc, w2_h, (long long)Cc * Ff, Ff, Cc);
    cudaEventRecord(eRestW, s2);

    for (int l = 0; l < Ll; l++) {
        float* atts_l = atts + (long long)l * HBTT;

        // LN1 (l==0 fuses add_pos; concurrent with qkv weight transpose)
        if (l == 0)
            ln_kernel<2><<<Mr, 256>>>(x, pos, h, xn, ln1_s, ln1_b);
        else
            ln_kernel<1><<<Mr, 256>>>(h, nullptr, nullptr, xn,
                                      ln1_s + l * Cc, ln1_b + l * Cc);

        if (l == 0) cudaStreamWaitEvent(0, eQkvW, 0);   // wqkv ready

        // QKV (K=1024): z = s*8+h (24). q,k: fp16 rows; v: vT via smem staging.
        gemm_mma<5, 16><<<dim3(1, 32, 24), 256, SM_MM>>>(
            xn, Cc, 1, 0, 0,
            wqkv_h + (long long)l * 3 * HDK, Cc, 1, DK, 0,
            (float*)qkv, Dd, 1, (long long)Mr * Dd, 0,
            nullptr);

        // fused scores + softmax + att@V (occ 2, 32-row q tiles)
        fused_attn<<<dim3(32, 32), 256, SM_ATT>>>(qkv, atts_l, o);

        if (l == 0) cudaStreamWaitEvent(0, eRestW, 0);  // Wo/W1/W2 ready

        // proj (K=1024): h += o @ Wo + bo
        gemm_mma<2, 16><<<dim3(8, 32, 1), 256, SM_MM>>>(
            o, Cc, 1, 0, 0,
            wo_h + (long long)l * Cc * Cc, Cc, 1, 0, 0,
            h, Cc, 1, 0, 0,
            bo + l * Cc);

        // LN2 -> xn fp16
        ln_kernel<1><<<Mr, 256>>>(h, nullptr, nullptr, xn,
                                  ln2_s + l * Cc, ln2_b + l * Cc);

        // FFN1 (K=1024): u = relu(xn @ W1 + b1) -> fp16
        gemm_mma<4, 16><<<dim3(32, 32, 1), 256, SM_MM>>>(
            xn, Cc, 1, 0, 0,
            w1_h + (long long)l * Cc * Ff, Cc, 1, 0, 0,
            (float*)u, Ff, 1, 0, 0,
            b1 + l * Ff);

        // FFN2 (K=4096): h += u @ W2 + b2
        gemm_mma<2, 64><<<dim3(8, 32, 1), 256, SM_MM>>>(
            u, Ff, 1, 0, 0,
            w2_h + (long long)l * Ff * Cc, Ff, 1, 0, 0,
            h, Cc, 1, 0, 0,
            b2 + l * Cc);
    }

    // final LN -> fp32 output (streaming store)
    ln_kernel<0><<<Mr, 256>>>(h, nullptr, outx, nullptr, lnf_s, lnf_b);
}

// round 17
// speedup vs baseline: 1.0527x; 1.0527x over previous
#include <cuda_runtime.h>
#include <cuda_fp16.h>
#include <cstdint>

// Problem constants
constexpr int Bb = 4, Ts = 1024, Cc = 1024, Hh = 8, Dd = 128, Ff = 4096, Ll = 4;
constexpr int Mr = Bb * Ts;  // 4096

// ---------------- scratch (device globals; allocation-free rule) ----------
__device__ float  g_h[(size_t)Mr * Cc];                    // residual fp32
__device__ __half g_qkv[(size_t)3 * Hh * Mr * Dd];         // q,k rows; vT cols
__device__ __half g_xn[(size_t)Mr * Cc];                   // LN out fp16
__device__ __half g_o[(size_t)Mr * Cc];                    // attn out fp16
__device__ __half g_u[(size_t)Mr * Ff];                    // FFN hidden fp16
__device__ __half g_wqkv_h[(size_t)Ll * 3 * Hh * Dd * Cc]; // fp16 weights [N,K]
__device__ __half g_wo_h[(size_t)Ll * Cc * Cc];
__device__ __half g_w1_h[(size_t)Ll * Cc * Ff];
__device__ __half g_w2_h[(size_t)Ll * Ff * Cc];

// ---------------- PTX helpers (sm_80-era; compiles for plain sm_103) ------
__device__ __forceinline__ uint32_t smem_u32(const void* p) {
    uint32_t a;
    asm("{ .reg .u64 t; cvta.to.shared.u64 t, %1; cvt.u32.u64 %0, t; }" : "=r"(a) : "l"(p));
    return a;
}
__device__ __forceinline__ void cp16(uint32_t s, const void* g) {
    asm volatile("cp.async.cg.shared.global [%0], [%1], 16;" :: "r"(s), "l"(g));
}
#define CP_COMMIT() asm volatile("cp.async.commit_group;" ::: "memory")
#define CP_WAIT(n)  asm volatile("cp.async.wait_group %0;" :: "n"(n) : "memory")

#define LDSM4(r, addr) \
    asm volatile("ldmatrix.sync.aligned.m8n8.x4.shared.b16 {%0,%1,%2,%3}, [%4];" \
        : "=r"((r)[0]), "=r"((r)[1]), "=r"((r)[2]), "=r"((r)[3]) : "r"(addr))

#define MMA16816(c, a, b) \
    asm volatile("mma.sync.aligned.m16n8k16.row.col.f32.f16.f16.f32 " \
        "{%0,%1,%2,%3}, {%4,%5,%6,%7}, {%8,%9}, {%0,%1,%2,%3};" \
        : "+f"((c)[0]), "+f"((c)[1]), "+f"((c)[2]), "+f"((c)[3]) \
        : "r"((a)[0]), "r"((a)[1]), "r"((a)[2]), "r"((a)[3]), \
          "r"((b)[0]), "r"((b)[1]))

// ---------------------------------------------------------------------------
// HMMA fp16 GEMM (proven R14/R15 config): C[M,N] = A[M,K] * Bt[N,K]^T.
// Block 128x128, 8 warps (4M x 2N), K-chunks of 64, 3-stage cp.async, occ 2.
// NCH = K/64 (compile-time trip count).
// EPI: 2 fp32 += acc+bias | 4 relu(acc+bias)->fp16 rows
//      5 QKV: z<16 fp16 rows, z>=16 vT transposed via smem staging (ld = Mr)
// ---------------------------------------------------------------------------
constexpr int STG   = 36864;            // 128 rows * 144 B * 2 matrices
constexpr int B_OFF = 18432;
constexpr int SM_MM = 3 * STG;          // 110592

template<int EPI, int NCH>
__global__ void __launch_bounds__(256, 2)
gemm_mma(const __half* __restrict__ A, int lda,
         int aDiv, long long aShi, long long aSlo,
         const __half* __restrict__ B, int ldb,
         int bDiv, long long bShi, long long bSlo,
         float* __restrict__ Cm, int ldc,
         int cDiv, long long cShi, long long cSlo,
         const float* __restrict__ bias)
{
    extern __shared__ char sm[];
    const uint32_t sb = smem_u32(sm);

    const int tid = threadIdx.x;
    const int lane = tid & 31;
    const int warp = tid >> 5;
    const int warpM = warp & 3;
    const int warpN = warp >> 2;

    const int z = blockIdx.z;
    A  += (long long)(z / aDiv) * aShi + (long long)(z % aDiv) * aSlo;
    B  += (long long)(z / bDiv) * bShi + (long long)(z % bDiv) * bSlo;
    const long long cOff = (long long)(z / cDiv) * cShi + (long long)(z % cDiv) * cSlo;

    const int rowBase = blockIdx.y * 128;
    const int colBase = blockIdx.x * 128;

    float acc[2][8][4];
#pragma unroll
    for (int i = 0; i < 2; i++)
#pragma unroll
        for (int j = 0; j < 8; j++)
#pragma unroll
            for (int q = 0; q < 4; q++) acc[i][j][q] = 0.f;

    const int ldr = tid >> 3;            // 0..31
    const int c16 = (tid & 7) * 16;      // byte col in 128B row

    auto load_chunk = [&](int i, int st) {
        const long long k0 = (long long)i * 64;
        const uint32_t sbase = sb + (uint32_t)st * STG;
#pragma unroll
        for (int g = 0; g < 4; g++) {
            const int rr = g * 32 + ldr;
            const uint32_t so = sbase + (uint32_t)(rr * 144 + c16);
            cp16(so,
                 (const char*)(A + (long long)(rowBase + rr) * lda + k0) + c16);
            cp16(so + B_OFF,
                 (const char*)(B + (long long)(colBase + rr) * ldb + k0) + c16);
        }
    };

    load_chunk(0, 0); CP_COMMIT();
    load_chunk(1, 1); CP_COMMIT();

#pragma unroll 4
    for (int i = 0; i < NCH; i++) {
        if (i + 1 < NCH) { CP_WAIT(1); } else { CP_WAIT(0); }
        __syncthreads();
        if (i + 2 < NCH) { load_chunk(i + 2, (i + 2) % 3); CP_COMMIT(); }

        const uint32_t sbase = sb + (uint32_t)(i % 3) * STG;
#pragma unroll
        for (int ks = 0; ks < 4; ks++) {
            uint32_t ah[2][4], bh[8][2];
#pragma unroll
            for (int tm = 0; tm < 2; tm++) {
                const int row = warpM * 32 + tm * 16 + (lane & 15);
                const uint32_t addr =
                    sbase + (uint32_t)(row * 144 + ((lane >> 4) << 4) + ks * 32);
                LDSM4(ah[tm], addr);
            }
#pragma unroll
            for (int gn = 0; gn < 4; gn++) {
                const int n = warpN * 64 + gn * 16 + ((lane >> 4) & 1) * 8 + (lane & 7);
                const uint32_t addr =
                    sbase + (uint32_t)B_OFF +
                    (uint32_t)(n * 144 + ((lane >> 3) & 1) * 16 + ks * 32);
                uint32_t r0[4];
                LDSM4(r0, addr);
                bh[gn * 2][0] = r0[0]; bh[gn * 2][1] = r0[1];
                bh[gn * 2 + 1][0] = r0[2]; bh[gn * 2 + 1][1] = r0[3];
            }
#pragma unroll
            for (int tm = 0; tm < 2; tm++) {
#pragma unroll
                for (int tn = 0; tn < 8; tn++) {
                    MMA16816(acc[tm][tn], ah[tm], bh[tn]);
                }
            }
        }
    }

    const int lr = lane >> 2;
    const int lc = (lane & 3) * 2;

    if (EPI == 5 && blockIdx.z >= 16) {
        // ---- vT epilogue: stage transposed tile in smem, coalesced store ----
        __syncthreads();
        __half* st = (__half*)sm;                // [128 cols][136 halves stride]
#pragma unroll
        for (int tm = 0; tm < 2; tm++) {
#pragma unroll
            for (int tn = 0; tn < 8; tn++) {
                const int lrow = warpM * 32 + tm * 16 + lr;
                const int lcol = warpN * 64 + tn * 8 + lc;
                const float* a = acc[tm][tn];
                st[lcol * 136 + lrow]           = __float2half_rn(a[0]);
                st[(lcol + 1) * 136 + lrow]     = __float2half_rn(a[1]);
                st[lcol * 136 + lrow + 8]       = __float2half_rn(a[2]);
                st[(lcol + 1) * 136 + lrow + 8] = __float2half_rn(a[3]);
            }
        }
        __syncthreads();
        __half* base = (__half*)Cm + cOff;
        const int cr = tid >> 1;
        const int part = tid & 1;
        const uint4* src = (const uint4*)((const char*)st + cr * 272 + part * 128);
        uint4* dst = (uint4*)(base + (long long)(colBase + cr) * Mr + rowBase + part * 64);
#pragma unroll
        for (int i = 0; i < 8; i++) dst[i] = src[i];
        return;
    }

    // ---- standard epilogues from registers ----
    const int rB = rowBase + warpM * 32;
    const int cB = colBase + warpN * 64;
#pragma unroll
    for (int tm = 0; tm < 2; tm++) {
#pragma unroll
        for (int tn = 0; tn < 8; tn++) {
            const int row0 = rB + tm * 16 + lr;
            const int col  = cB + tn * 8 + lc;
            const float* a = acc[tm][tn];
            if (EPI == 2) {
                const float b0 = bias[col], b1 = bias[col + 1];
                float* p0 = Cm + cOff + (long long)row0 * ldc + col;
                float* p1 = Cm + cOff + (long long)(row0 + 8) * ldc + col;
                p0[0] += a[0] + b0;  p0[1] += a[1] + b1;
                p1[0] += a[2] + b0;  p1[1] += a[3] + b1;
            } else if (EPI == 4) {
                const float b0 = bias[col], b1 = bias[col + 1];
                __half* ph = (__half*)Cm + cOff;
#pragma unroll
                for (int half_ = 0; half_ < 2; half_++) {
                    float t0 = a[half_ * 2 + 0] + b0;
                    float t1 = a[half_ * 2 + 1] + b1;
                    t0 = t0 > 0.f ? t0 : 0.f;
                    t1 = t1 > 0.f ? t1 : 0.f;
                    *(__half2*)(ph + (long long)(row0 + half_ * 8) * ldc + col) =
                        __halves2half2(__float2half_rn(t0), __float2half_rn(t1));
                }
            } else {  // EPI 5 (q,k): fp16 row store
                __half* ph = (__half*)Cm + cOff;
#pragma unroll
                for (int half_ = 0; half_ < 2; half_++) {
                    *(__half2*)(ph + (long long)(row0 + half_ * 8) * ldc + col) =
                        __halves2half2(__float2half_rn(a[half_ * 2 + 0]),
                                       __float2half_rn(a[half_ * 2 + 1]));
                }
            }
        }
    }
}

// ---------------------------------------------------------------------------
// Fused attention (R15 layout, 512 threads): per block = (h, b, 64 q-rows).
// 16 warps = 4 M-warps (16 rows) x 4 N-warps (32 cols).
// Phase 1: S[64,1024] = q·k^T (8 k-tiles of 128 rows, 2-stage).
// Softmax (warp per 4 rows): fp32 atts (float4 streaming) + fp16 probs.
// Phase 2: O[64,128] = P·vT (8 chunks of 128 k-cols, 2-stage).
// smem: probs 64x2064 | q 64x272 | kv 2x34816.  Total 219136 B, occ 1.
// ---------------------------------------------------------------------------
constexpr int PR_STRIDE = 2064;                  // 2048 + 16 pad
constexpr int Q_OFF  = 64 * PR_STRIDE;           // 132096
constexpr int KV_OFF = Q_OFF + 64 * 272;         // 149504
constexpr int SM_ATT = KV_OFF + 2 * 34816;       // 219136

__global__ void __launch_bounds__(512, 1)
fused_attn(const __half* __restrict__ qkv, float* __restrict__ atts_l,
           __half* __restrict__ o)
{
    extern __shared__ char sm[];
    const uint32_t sb = smem_u32(sm);

    const int tid = threadIdx.x;
    const int lane = tid & 31;
    const int warp = tid >> 5;       // 0..15
    const int warpM = warp & 3;      // 4 M-warps (16 rows each)
    const int warpN = warp >> 2;     // 4 N-warps (32 cols each)

    const int qt = blockIdx.x;       // q tile (64 rows): 0..15
    const int hb = blockIdx.y;       // h*Bb + b: 0..31
    const int hh = hb >> 2, bb = hb & 3;

    const long long MrD = (long long)Mr * Dd;
    const __half* qbase = qkv + hh * MrD + (long long)(bb * Ts + qt * 64) * Dd;
    const __half* kbase = qkv + (long long)Hh * MrD + hh * MrD + (long long)(bb * Ts) * Dd;
    const __half* vbase = qkv + 2ll * Hh * MrD + hh * MrD + (long long)(bb * Ts);

    const uint32_t qs = sb + Q_OFF;
    const uint32_t kv = sb + KV_OFF;

    // ---- load q tile (64 rows x 256 B): 512 thr, 2 cp16 each ----
    {
        const int r = tid >> 3;              // 0..63
        const int c = (tid & 7) * 16;        // 0..112
        cp16(qs + (uint32_t)(r * 272 + c),       (const char*)(qbase + (long long)r * Dd) + c);
        cp16(qs + (uint32_t)(r * 272 + c + 128), (const char*)(qbase + (long long)r * Dd) + c + 128);
    }
    CP_COMMIT();

    // k tile = 128 seq rows x 256 B (stride 272)
    auto load_k = [&](int kt, int st) {
        const int r = tid >> 2;              // 0..127
        const int c = (tid & 3) * 16;        // 0..48
        const char* src = (const char*)(kbase + (long long)(kt * 128 + r) * Dd);
        const uint32_t dst = kv + (uint32_t)st * 34816 + (uint32_t)(r * 272);
#pragma unroll
        for (int g = 0; g < 4; g++)
            cp16(dst + c + g * 64, src + c + g * 64);
    };
    // v chunk = 128 d-rows x 128 k-cols (256 B payload / row, stride 272)
    auto load_v = [&](int kc, int st) {
        const int r = tid >> 2;              // 0..127
        const int c = (tid & 3) * 16;
        const char* src = (const char*)(vbase + (long long)r * Mr + kc * 128);
        const uint32_t dst = kv + (uint32_t)st * 34816 + (uint32_t)(r * 272);
#pragma unroll
        for (int g = 0; g < 4; g++)
            cp16(dst + c + g * 64, src + c + g * 64);
    };

    const int lr = lane >> 2;
    const int lc = (lane & 3) * 2;

    // ================= phase 1: scores =================
    load_k(0, 0); CP_COMMIT();
    for (int kt = 0; kt < 8; kt++) {
        CP_WAIT(0);
        __syncthreads();
        if (kt + 1 < 8) { load_k(kt + 1, (kt + 1) & 1); CP_COMMIT(); }

        const uint32_t kbuf = kv + (uint32_t)(kt & 1) * 34816;
        float acc[4][4];
#pragma unroll
        for (int j = 0; j < 4; j++)
#pragma unroll
            for (int q = 0; q < 4; q++) acc[j][q] = 0.f;

#pragma unroll
        for (int ks = 0; ks < 8; ks++) {
            uint32_t ah[4], bh[4][2];
            {
                const int row = warpM * 16 + (lane & 15);
                LDSM4(ah, qs + (uint32_t)(row * 272 + ((lane >> 4) << 4) + ks * 32));
            }
#pragma unroll
            for (int gn = 0; gn < 2; gn++) {
                const int n = warpN * 32 + gn * 16 + ((lane >> 4) & 1) * 8 + (lane & 7);
                uint32_t r0[4];
                LDSM4(r0, kbuf + (uint32_t)(n * 272 + ((lane >> 3) & 1) * 16 + ks * 32));
                bh[gn * 2][0] = r0[0]; bh[gn * 2][1] = r0[1];
                bh[gn * 2 + 1][0] = r0[2]; bh[gn * 2 + 1][1] = r0[3];
            }
#pragma unroll
            for (int tn = 0; tn < 4; tn++)
                MMA16816(acc[tn], ah, bh[tn]);
        }

        // store fp16 scores into probs smem
#pragma unroll
        for (int tn = 0; tn < 4; tn++) {
            const int row0 = warpM * 16 + lr;
            const int col = kt * 128 + warpN * 32 + tn * 8 + lc;
            const float* a = acc[tn];
#pragma unroll
            for (int half_ = 0; half_ < 2; half_++) {
                *(__half2*)(sm + (row0 + half_ * 8) * PR_STRIDE + col * 2) =
                    __halves2half2(__float2half_rn(a[half_ * 2 + 0]),
                                   __float2half_rn(a[half_ * 2 + 1]));
            }
        }
    }
    __syncthreads();   // all scores in smem

    load_v(0, 0); CP_COMMIT();

    // ================= softmax (warp per 4 rows, coalesced) =================
    {
        const float sc = 0.08838834764831845f;  // 1/sqrt(128)
        for (int rr = 0; rr < 4; rr++) {
            const int row = warp * 4 + rr;
            __half2* prow = (__half2*)(sm + row * PR_STRIDE);
            float v[32];
            float mx = -1e30f;
#pragma unroll
            for (int j = 0; j < 8; j++) {
                const int idx = j * 64 + lane * 2;
                const __half2 a2 = prow[idx];
                const __half2 b2 = prow[idx + 1];
                float f0 = __half2float(__low2half(a2)) * sc;
                float f1 = __half2float(__high2half(a2)) * sc;
                float f2 = __half2float(__low2half(b2)) * sc;
                float f3 = __half2float(__high2half(b2)) * sc;
                v[4 * j] = f0; v[4 * j + 1] = f1; v[4 * j + 2] = f2; v[4 * j + 3] = f3;
                mx = fmaxf(mx, fmaxf(fmaxf(f0, f1), fmaxf(f2, f3)));
            }
#pragma unroll
            for (int off = 16; off; off >>= 1)
                mx = fmaxf(mx, __shfl_xor_sync(0xFFFFFFFFu, mx, off));
            float s = 0.f;
#pragma unroll
            for (int i = 0; i < 32; i++) { v[i] = __expf(v[i] - mx); s += v[i]; }
#pragma unroll
            for (int off = 16; off; off >>= 1)
                s += __shfl_xor_sync(0xFFFFFFFFu, s, off);
            const float inv = 1.f / s;

            float* arow = atts_l + ((long long)hb * Ts + qt * 64 + row) * 1024;
#pragma unroll
            for (int j = 0; j < 8; j++) {
                const int idx = j * 64 + lane * 2;
                const float f0 = v[4 * j] * inv, f1 = v[4 * j + 1] * inv;
                const float f2 = v[4 * j + 2] * inv, f3 = v[4 * j + 3] * inv;
                prow[idx]     = __halves2half2(__float2half_rn(f0), __float2half_rn(f1));
                prow[idx + 1] = __halves2half2(__float2half_rn(f2), __float2half_rn(f3));
                float4 o4 = {f0, f1, f2, f3};
                __stcs((float4*)(arow + j * 128 + lane * 4), o4);
            }
        }
    }
    __syncthreads();

    // ================= phase 2: O = P @ vT (8 chunks of 128 cols) ==========
    float acc2[4][4];
#pragma unroll
    for (int j = 0; j < 4; j++)
#pragma unroll
        for (int q = 0; q < 4; q++) acc2[j][q] = 0.f;

    for (int kc = 0; kc < 8; kc++) {
        CP_WAIT(0);
        __syncthreads();
        if (kc + 1 < 8) { load_v(kc + 1, (kc + 1) & 1); CP_COMMIT(); }

        const uint32_t vbuf = kv + (uint32_t)(kc & 1) * 34816;
#pragma unroll
        for (int ks = 0; ks < 8; ks++) {
            uint32_t ah[4], bh[4][2];
            {
                const int row = warpM * 16 + (lane & 15);
                LDSM4(ah, sb + (uint32_t)(row * PR_STRIDE + kc * 256 +
                                          ((lane >> 4) << 4) + ks * 32));
            }
#pragma unroll
            for (int gn = 0; gn < 2; gn++) {
                const int n = warpN * 32 + gn * 16 + ((lane >> 4) & 1) * 8 + (lane & 7);
                uint32_t r0[4];
                LDSM4(r0, vbuf + (uint32_t)(n * 272 + ((lane >> 3) & 1) * 16 + ks * 32));
                bh[gn * 2][0] = r0[0]; bh[gn * 2][1] = r0[1];
                bh[gn * 2 + 1][0] = r0[2]; bh[gn * 2 + 1][1] = r0[3];
            }
#pragma unroll
            for (int tn = 0; tn < 4; tn++)
                MMA16816(acc2[tn], ah, bh[tn]);
        }
    }

    // epilogue: o fp16 concat layout [B*T, C]
#pragma unroll
    for (int tn = 0; tn < 4; tn++) {
        const int row0 = warpM * 16 + lr;
        const int col = warpN * 32 + tn * 8 + lc;
        const float* a = acc2[tn];
#pragma unroll
        for (int half_ = 0; half_ < 2; half_++) {
            const long long grow = (long long)(bb * Ts + qt * 64 + row0 + half_ * 8);
            *(__half2*)(o + grow * Cc + hh * 128 + col) =
                __halves2half2(__float2half_rn(a[half_ * 2 + 0]),
                               __float2half_rn(a[half_ * 2 + 1]));
        }
    }
}

// ---------------------------------------------------------------------------
// 64x64-tile weight transpose + fp16 convert, float4 loads, 8B stores.
// ---------------------------------------------------------------------------
__global__ void __launch_bounds__(256)
transpose64(const float* __restrict__ W, long long inSlo,
            __half* __restrict__ out, long long outSlo, int K, int N)
{
    const int z = blockIdx.z;
    W += (long long)z * inSlo;
    const long long oOff = (long long)z * outSlo;
    __shared__ float t[64][65];
    const int r  = threadIdx.x >> 4;
    const int c4 = threadIdx.x & 15;
    const int n0 = blockIdx.x * 64, k0 = blockIdx.y * 64;
#pragma unroll
    for (int i = 0; i < 4; i++) {
        const int row = i * 16 + r;
        float4 v = *(const float4*)(W + (long long)(k0 + row) * N + n0 + c4 * 4);
        t[c4 * 4 + 0][row] = v.x;
        t[c4 * 4 + 1][row] = v.y;
        t[c4 * 4 + 2][row] = v.z;
        t[c4 * 4 + 3][row] = v.w;
    }
    __syncthreads();
#pragma unroll
    for (int i = 0; i < 4; i++) {
        const int n = i * 16 + r;
        const float f0 = t[n][c4 * 4 + 0];
        const float f1 = t[n][c4 * 4 + 1];
        const float f2 = t[n][c4 * 4 + 2];
        const float f3 = t[n][c4 * 4 + 3];
        __half2* dst = (__half2*)(out + oOff + (long long)(n0 + n) * K + k0 + c4 * 4);
        dst[0] = __halves2half2(__float2half_rn(f0), __float2half_rn(f1));
        dst[1] = __halves2half2(__float2half_rn(f2), __float2half_rn(f3));
    }
}

// Merged QKV weight transpose (64x64 tiles): z in [0,96).
__global__ void __launch_bounds__(256)
transpose_qkv64(const float* __restrict__ Wq, const float* __restrict__ Wk,
                const float* __restrict__ Wv, __half* __restrict__ outw)
{
    const long long DK  = (long long)Dd * Cc;
    const long long HDK = Hh * DK;
    const int z = blockIdx.z;
    const int s = z >> 5;
    const int zz = z & 31;
    const float* W = (s == 0 ? Wq : s == 1 ? Wk : Wv) + (long long)zz * DK;
    const int l = zz >> 3, hd = zz & 7;
    __half* outp = outw + (long long)l * 3 * HDK + (long long)s * HDK + (long long)hd * DK;

    __shared__ float t[64][65];
    const int r  = threadIdx.x >> 4;
    const int c4 = threadIdx.x & 15;
    const int n0 = blockIdx.x * 64, k0 = blockIdx.y * 64;
#pragma unroll
    for (int i = 0; i < 4; i++) {
        const int row = i * 16 + r;
        float4 v = *(const float4*)(W + (long long)(k0 + row) * Dd + n0 + c4 * 4);
        t[c4 * 4 + 0][row] = v.x;
        t[c4 * 4 + 1][row] = v.y;
        t[c4 * 4 + 2][row] = v.z;
        t[c4 * 4 + 3][row] = v.w;
    }
    __syncthreads();
#pragma unroll
    for (int i = 0; i < 4; i++) {
        const int n = i * 16 + r;
        const float f0 = t[n][c4 * 4 + 0];
        const float f1 = t[n][c4 * 4 + 1];
        const float f2 = t[n][c4 * 4 + 2];
        const float f3 = t[n][c4 * 4 + 3];
        __half2* dst = (__half2*)(outp + (long long)(n0 + n) * Cc + k0 + c4 * 4);
        dst[0] = __halves2half2(__float2half_rn(f0), __float2half_rn(f1));
        dst[1] = __halves2half2(__float2half_rn(f2), __float2half_rn(f3));
    }
}

// ---------------------------------------------------------------------------
// LayerNorm (warp-shuffle reductions).
// MODE 0: fp32 out (streaming). MODE 1: fp16 out. MODE 2: x+pos fused.
// ---------------------------------------------------------------------------
template<int MODE>
__global__ void __launch_bounds__(256)
ln_kernel(const float* __restrict__ x, const float* __restrict__ pos,
          float* __restrict__ y, __half* __restrict__ yh,
          const float* __restrict__ s, const float* __restrict__ b)
{
    __shared__ float red[16];
    const int tid = threadIdx.x;
    const int lane = tid & 31;
    const int warp = tid >> 5;
    const long long row = blockIdx.x;

    float4 v = *(const float4*)(x + row * 1024 + tid * 4);
    if (MODE == 2) {
        const long long prow = row & (Ts - 1);
        float4 p = *(const float4*)(pos + prow * 1024 + tid * 4);
        v.x += p.x; v.y += p.y; v.z += p.z; v.w += p.w;
        *(float4*)(y + row * 1024 + tid * 4) = v;
    }

    float sm1 = v.x + v.y + v.z + v.w;
#pragma unroll
    for (int off = 16; off; off >>= 1)
        sm1 += __shfl_xor_sync(0xFFFFFFFFu, sm1, off);
    if (lane == 0) red[warp] = sm1;
    __syncthreads();
    float tot = 0.f;
#pragma unroll
    for (int w = 0; w < 8; w++) tot += red[w];
    const float mean = tot * (1.f / 1024.f);

    float dx = v.x - mean, dy = v.y - mean, dz = v.z - mean, dw = v.w - mean;
    float sm2 = dx * dx + dy * dy + dz * dz + dw * dw;
#pragma unroll
    for (int off = 16; off; off >>= 1)
        sm2 += __shfl_xor_sync(0xFFFFFFFFu, sm2, off);
    if (lane == 0) red[8 + warp] = sm2;
    __syncthreads();
    float tot2 = 0.f;
#pragma unroll
    for (int w = 0; w < 8; w++) tot2 += red[8 + w];
    const float rs = rsqrtf(tot2 * (1.f / 1024.f) + 1e-5f);

    const int c = tid * 4;
    float t0 = dx * rs * s[c + 0] + b[c + 0];
    float t1 = dy * rs * s[c + 1] + b[c + 1];
    float t2 = dz * rs * s[c + 2] + b[c + 2];
    float t3 = dw * rs * s[c + 3] + b[c + 3];
    if (MODE == 0) {
        float4 o4 = {t0, t1, t2, t3};
        __stcs((float4*)(y + row * 1024 + c), o4);
    } else {
        __half* ph = yh + row * 1024 + c;
        *(__half2*)ph = __halves2half2(__float2half_rn(t0), __float2half_rn(t1));
        *(__half2*)(ph + 2) = __halves2half2(__float2half_rn(t2), __float2half_rn(t3));
    }
}

// ---------------------------------------------------------------------------
extern "C" void kernel_launch(void* const* d_in, const int* in_sizes, int n_in,
                              void* d_out, int out_size)
{
    const float* x     = (const float*)d_in[0];
    const float* pos   = (const float*)d_in[1];
    const float* Wq    = (const float*)d_in[2];
    const float* Wk    = (const float*)d_in[3];
    const float* Wv    = (const float*)d_in[4];
    const float* Wo    = (const float*)d_in[5];
    const float* bo    = (const float*)d_in[6];
    const float* ln1_s = (const float*)d_in[7];
    const float* ln1_b = (const float*)d_in[8];
    const float* ln2_s = (const float*)d_in[9];
    const float* ln2_b = (const float*)d_in[10];
    const float* W1    = (const float*)d_in[11];
    const float* b1    = (const float*)d_in[12];
    const float* W2    = (const float*)d_in[13];
    const float* b2    = (const float*)d_in[14];
    const float* lnf_s = (const float*)d_in[15];
    const float* lnf_b = (const float*)d_in[16];

    float* out  = (float*)d_out;
    float* outx = out;
    float* atts = out + (long long)Mr * Cc;

    float* h;
    __half *qkv, *xn, *o, *u, *wqkv_h, *wo_h, *w1_h, *w2_h;
    cudaGetSymbolAddress((void**)&h,      g_h);
    cudaGetSymbolAddress((void**)&qkv,    g_qkv);
    cudaGetSymbolAddress((void**)&xn,     g_xn);
    cudaGetSymbolAddress((void**)&o,      g_o);
    cudaGetSymbolAddress((void**)&u,      g_u);
    cudaGetSymbolAddress((void**)&wqkv_h, g_wqkv_h);
    cudaGetSymbolAddress((void**)&wo_h,   g_wo_h);
    cudaGetSymbolAddress((void**)&w1_h,   g_w1_h);
    cudaGetSymbolAddress((void**)&w2_h,   g_w2_h);

    cudaFuncSetAttribute((const void*)gemm_mma<2, 16>, cudaFuncAttributeMaxDynamicSharedMemorySize, SM_MM);
    cudaFuncSetAttribute((const void*)gemm_mma<2, 64>, cudaFuncAttributeMaxDynamicSharedMemorySize, SM_MM);
    cudaFuncSetAttribute((const void*)gemm_mma<4, 16>, cudaFuncAttributeMaxDynamicSharedMemorySize, SM_MM);
    cudaFuncSetAttribute((const void*)gemm_mma<5, 16>, cudaFuncAttributeMaxDynamicSharedMemorySize, SM_MM);
    cudaFuncSetAttribute((const void*)fused_attn, cudaFuncAttributeMaxDynamicSharedMemorySize, SM_ATT);

    const long long DK   = (long long)Dd * Cc;       // 131072
    const long long HDK  = Hh * DK;
    const long long HBTT = (long long)Hh * Bb * Ts * Ts;

    // ---- fork a side stream (graph-capturable event fork/join) ----
    cudaStream_t s2;
    cudaStreamCreateWithFlags(&s2, cudaStreamNonBlocking);
    cudaEvent_t eFork, eQkvW, eRestW;
    cudaEventCreateWithFlags(&eFork,  cudaEventDisableTiming);
    cudaEventCreateWithFlags(&eQkvW,  cudaEventDisableTiming);
    cudaEventCreateWithFlags(&eRestW, cudaEventDisableTiming);

    cudaEventRecord(eFork, 0);
    cudaStreamWaitEvent(s2, eFork, 0);

    // side stream: weight transposes
    transpose_qkv64<<<dim3(Dd / 64, Cc / 64, 96), 256, 0, s2>>>(Wq, Wk, Wv, wqkv_h);
    cudaEventRecord(eQkvW, s2);
    transpose64<<<dim3(Cc / 64, Cc / 64, Ll), 256, 0, s2>>>(
        Wo, (long long)Cc * Cc, wo_h, (long long)Cc * Cc, Cc, Cc);
    transpose64<<<dim3(Ff / 64, Cc / 64, Ll), 256, 0, s2>>>(
        W1, (long long)Cc * Ff, w1_h, (long long)Ff * Cc, Cc, Ff);
    transpose64<<<dim3(Cc / 64, Ff / 64, Ll), 256, 0, s2>>>(
        W2, (long long)Ff * Cc, w2_h, (long long)Cc * Ff, Ff, Cc);
    cudaEventRecord(eRestW, s2);

    for (int l = 0; l < Ll; l++) {
        float* atts_l = atts + (long long)l * HBTT;

        // LN1 (l==0 fuses add_pos; concurrent with qkv weight transpose)
        if (l == 0)
            ln_kernel<2><<<Mr, 256>>>(x, pos, h, xn, ln1_s, ln1_b);
        else
            ln_kernel<1><<<Mr, 256>>>(h, nullptr, nullptr, xn,
                                      ln1_s + l * Cc, ln1_b + l * Cc);

        if (l == 0) cudaStreamWaitEvent(0, eQkvW, 0);   // wqkv ready

        // QKV (K=1024): z = s*8+h (24). q,k: fp16 rows; v: vT via smem staging.
        gemm_mma<5, 16><<<dim3(1, 32, 24), 256, SM_MM>>>(
            xn, Cc, 1, 0, 0,
            wqkv_h + (long long)l * 3 * HDK, Cc, 1, DK, 0,
            (float*)qkv, Dd, 1, (long long)Mr * Dd, 0,
            nullptr);

        // fused scores + softmax + att@V (64-row q tiles, 512 threads)
        fused_attn<<<dim3(16, 32), 512, SM_ATT>>>(qkv, atts_l, o);

        if (l == 0) cudaStreamWaitEvent(0, eRestW, 0);  // Wo/W1/W2 ready

        // proj (K=1024): h += o @ Wo + bo
        gemm_mma<2, 16><<<dim3(8, 32, 1), 256, SM_MM>>>(
            o, Cc, 1, 0, 0,
            wo_h + (long long)l * Cc * Cc, Cc, 1, 0, 0,
            h, Cc, 1, 0, 0,
            bo + l * Cc);

        // LN2 -> xn fp16
        ln_kernel<1><<<Mr, 256>>>(h, nullptr, nullptr, xn,
                                  ln2_s + l * Cc, ln2_b + l * Cc);

        // FFN1 (K=1024): u = relu(xn @ W1 + b1) -> fp16
        gemm_mma<4, 16><<<dim3(32, 32, 1), 256, SM_MM>>>(
            xn, Cc, 1, 0, 0,
            w1_h + (long long)l * Cc * Ff, Cc, 1, 0, 0,
            (float*)u, Ff, 1, 0, 0,
            b1 + l * Ff);

        // FFN2 (K=4096): h += u @ W2 + b2
        gemm_mma<2, 64><<<dim3(8, 32, 1), 256, SM_MM>>>(
            u, Ff, 1, 0, 0,
            w2_h + (long long)l * Ff * Cc, Ff, 1, 0, 0,
            h, Cc, 1, 0, 0,
            b2 + l * Cc);
    }

    // final LN -> fp32 output (streaming store)
    ln_kernel<0><<<Mr, 256>>>(h, nullptr, outx, nullptr, lnf_s, lnf_b);
}